// round 11
// baseline (speedup 1.0000x reference)
#include <cuda_runtime.h>
#include <cuda_bf16.h>

#define IMG_H 256
#define IMG_W 256
#define NB 4
#define NK 4

#define TILE_W 128
#define TILE_H 4
#define SM_W   136         // cols tx0-4 .. tx0+131 (16B-aligned halo)
#define SM_H   6           // TILE_H + 2 bottom halo
#define NVEC   (SM_W / 4)  // 34 float4 spans per row
#define NSPAN  (SM_H * NVEC)   // 204
#define NTHREADS 128
#define GRID_BLOCKS ((IMG_W / TILE_W) * (IMG_H / TILE_H) * NB)   // 2*64*4 = 512

__device__ float        g_acc[NB][8];
__device__ unsigned int g_ticket;

__device__ __constant__ const int   PDY[10] = { 0, 0, 1, 1, 1, 1, 1, 2, 2, 2 };
__device__ __constant__ const int   PDX[10] = { 1, 2, -2, -1, 0, 1, 2, -1, 0, 1 };
__device__ __constant__ const float PDWc[10] = {
    0.93941306f, 0.77880078f,
    0.73161563f, 0.88249690f, 0.93941306f, 0.88249690f, 0.73161563f,
    0.73161563f, 0.77880078f, 0.73161563f
};

// enc bank-conflict swizzle: spreads lane-stride-4 granule accesses over all
// 8 bank groups. Involution within each 8-granule span.
__device__ __forceinline__ int swz(int c) { return c ^ ((c >> 3) & 7); }

__global__ __launch_bounds__(NTHREADS, 4)
void sncl_fused_kernel(const float* __restrict__ image,
                       const float* __restrict__ enc,
                       float* __restrict__ out) {
    const int b   = blockIdx.z;
    const int tx0 = blockIdx.x * TILE_W;
    const int ty0 = blockIdx.y * TILE_H;

    __shared__ float  sgray[SM_H][SM_W];
    __shared__ float4 senc [SM_H][SM_W];   // stored at swizzled column index
    __shared__ float  part [4][8];

    const int tid = threadIdx.y * 32 + threadIdx.x;   // blockDim = (32,4)
    const float* img0 = image + (size_t)b * 3 * IMG_H * IMG_W;
    const float* e0   = enc   + (size_t)b * 4 * IMG_H * IMG_W;
    const int HW = IMG_H * IMG_W;

    // Halo fill: 6 rows x 34 float4-spans. OOB span => 0 (zero padding).
    #pragma unroll
    for (int i = tid; i < NSPAN; i += NTHREADS) {
        int r  = i / NVEC;
        int v  = i - r * NVEC;
        int gy = ty0 + r;
        int gx = tx0 - 4 + v * 4;

        float4 i0 = make_float4(0.f,0.f,0.f,0.f), i1 = i0, i2 = i0;
        float4 c0 = i0, c1 = i0, c2 = i0, c3 = i0;
        if (gy < IMG_H && (unsigned)gx < (unsigned)IMG_W) {
            int off = gy * IMG_W + gx;
            i0 = *(const float4*)(img0 + off);
            i1 = *(const float4*)(img0 + HW + off);
            i2 = *(const float4*)(img0 + 2 * HW + off);
            c0 = *(const float4*)(e0 + off);
            c1 = *(const float4*)(e0 + HW + off);
            c2 = *(const float4*)(e0 + 2 * HW + off);
            c3 = *(const float4*)(e0 + 3 * HW + off);
        }
        float4 g4;
        g4.x = (i0.x + i1.x + i2.x) * (1.0f / 3.0f);
        g4.y = (i0.y + i1.y + i2.y) * (1.0f / 3.0f);
        g4.z = (i0.z + i1.z + i2.z) * (1.0f / 3.0f);
        g4.w = (i0.w + i1.w + i2.w) * (1.0f / 3.0f);
        *(float4*)&sgray[r][v * 4] = g4;
        int cbase = v * 4;
        senc[r][swz(cbase + 0)] = make_float4(c0.x, c1.x, c2.x, c3.x);
        senc[r][swz(cbase + 1)] = make_float4(c0.y, c1.y, c2.y, c3.y);
        senc[r][swz(cbase + 2)] = make_float4(c0.z, c1.z, c2.z, c3.z);
        senc[r][swz(cbase + 3)] = make_float4(c0.w, c1.w, c2.w, c3.w);
    }
    __syncthreads();

    // Each thread: 4 adjacent pixels in row y, columns lc0..lc0+3.
    const int y   = threadIdx.y;
    const int lc0 = threadIdx.x * 4 + 4;
    const int gx0 = tx0 + threadIdx.x * 4;
    const int gy  = ty0 + y;

    float4 cg4 = *(const float4*)&sgray[y][lc0];
    float  cv[4] = {cg4.x, cg4.y, cg4.z, cg4.w};
    float4 ec[4];
    #pragma unroll
    for (int i = 0; i < 4; i++) ec[i] = senc[y][swz(lc0 + i)];

    float  wsum[4] = {0.f, 0.f, 0.f, 0.f};
    float4 nom [4];
    #pragma unroll
    for (int i = 0; i < 4; i++) nom[i] = make_float4(0.f, 0.f, 0.f, 0.f);

    // tap: center i, neighbor (g,e), spatial weight DW
    #define TAP(i, g, e, DW) do {                                             \
        float d_ = (g) - cv[i];                                               \
        float w_ = fmaf(d_ * d_, (DW) * -0.01f, (DW));                        \
        wsum[i] += w_;                                                        \
        nom[i].x = fmaf(w_, (e).x, nom[i].x);                                 \
        nom[i].y = fmaf(w_, (e).y, nom[i].y);                                 \
        nom[i].z = fmaf(w_, (e).z, nom[i].z);                                 \
        nom[i].w = fmaf(w_, (e).w, nom[i].w);                                 \
    } while (0)

    // ---- dy = 0, dx in {1,2} ----
    {
        float4 grR = *(const float4*)&sgray[y][lc0 + 4];
        float  gz[8] = {cv[0], cv[1], cv[2], cv[3], grR.x, grR.y, grR.z, grR.w};
        float4 ez[6];
        ez[0] = ec[0]; ez[1] = ec[1]; ez[2] = ec[2]; ez[3] = ec[3];
        ez[4] = senc[y][swz(lc0 + 4)];
        ez[5] = senc[y][swz(lc0 + 5)];
        #pragma unroll
        for (int i = 0; i < 4; i++) {
            TAP(i, gz[i + 1], ez[i + 1], 0.93941306f);
            TAP(i, gz[i + 2], ez[i + 2], 0.77880078f);
        }
    }

    // ---- dy = 1, dx in [-2,2] ----
    {
        const float* row = sgray[y + 1];
        float4 a  = *(const float4*)(row + lc0 - 4);
        float4 bb = *(const float4*)(row + lc0);
        float4 cc = *(const float4*)(row + lc0 + 4);
        float g1[12] = {a.x,a.y,a.z,a.w, bb.x,bb.y,bb.z,bb.w, cc.x,cc.y,cc.z,cc.w};
        float4 E[8];
        #pragma unroll
        for (int j = 0; j < 8; j++) E[j] = senc[y + 1][swz(lc0 - 2 + j)];
        const float W1[5] = {0.73161563f, 0.88249690f, 0.93941306f,
                             0.88249690f, 0.73161563f};
        #pragma unroll
        for (int i = 0; i < 4; i++) {
            #pragma unroll
            for (int t = 0; t < 5; t++)
                TAP(i, g1[2 + i + t], E[i + t], W1[t]);
        }
    }

    // ---- dy = 2, dx in [-1,1] ----
    {
        const float* row = sgray[y + 2];
        float4 a  = *(const float4*)(row + lc0 - 4);
        float4 bb = *(const float4*)(row + lc0);
        float4 cc = *(const float4*)(row + lc0 + 4);
        float g2[12] = {a.x,a.y,a.z,a.w, bb.x,bb.y,bb.z,bb.w, cc.x,cc.y,cc.z,cc.w};
        float4 E[6];
        #pragma unroll
        for (int j = 0; j < 6; j++) E[j] = senc[y + 2][swz(lc0 - 1 + j)];
        const float W2[3] = {0.73161563f, 0.77880078f, 0.73161563f};
        #pragma unroll
        for (int i = 0; i < 4; i++) {
            #pragma unroll
            for (int t = 0; t < 3; t++)
                TAP(i, g2[3 + i + t], E[i + t], W2[t]);
        }
    }
    #undef TAP

    // ---- per-pixel epilogue ----
    float acc[8];
    #pragma unroll
    for (int j = 0; j < 8; j++) acc[j] = 0.0f;

    #pragma unroll
    for (int i = 0; i < 4; i++) {
        const int gxi = gx0 + i;
        float add = 1.0f;
        if (gy < 2 || gxi < 2 || gxi > IMG_W - 3) {
            // Negative-direction OOB taps: neighbor gray = 0 => common factor
            // exp(-c^2/100); sum the spatial weights of the OOB offsets.
            float S = 0.0f;
            #pragma unroll
            for (int p = 0; p < 10; p++) {
                int ny = gy - PDY[p];
                int nx = gxi - PDX[p];
                if (ny < 0 || (unsigned)nx >= (unsigned)IMG_W) S += PDWc[p];
            }
            add = fmaf(S, fmaf(cv[i] * cv[i], -0.01f, 1.0f), 1.0f);
        }
        float wd = wsum[i] + add;
        // num: ec o (2*nom) [both pair sides] + ec o ec [center]
        acc[0] = fmaf(ec[i].x, fmaf(2.0f, nom[i].x, ec[i].x), acc[0]);
        acc[1] = fmaf(ec[i].y, fmaf(2.0f, nom[i].y, ec[i].y), acc[1]);
        acc[2] = fmaf(ec[i].z, fmaf(2.0f, nom[i].z, ec[i].z), acc[2]);
        acc[3] = fmaf(ec[i].w, fmaf(2.0f, nom[i].w, ec[i].w), acc[3]);
        // den: ec*(pair weights + center + OOB) + nom (e_j side of pairs)
        acc[4] += fmaf(ec[i].x, wd, nom[i].x);
        acc[5] += fmaf(ec[i].y, wd, nom[i].y);
        acc[6] += fmaf(ec[i].z, wd, nom[i].z);
        acc[7] += fmaf(ec[i].w, wd, nom[i].w);
    }

    // Warp shuffle reduce (warp == threadIdx.y)
    #pragma unroll
    for (int o = 16; o > 0; o >>= 1) {
        #pragma unroll
        for (int j = 0; j < 8; j++)
            acc[j] += __shfl_down_sync(0xffffffffu, acc[j], o);
    }
    if (threadIdx.x == 0) {
        #pragma unroll
        for (int j = 0; j < 8; j++)
            part[threadIdx.y][j] = acc[j];
    }
    __syncthreads();

    if (tid < 8) {
        float s = part[0][tid] + part[1][tid] + part[2][tid] + part[3][tid];
        atomicAdd(&g_acc[b][tid], s);
    }
    __syncthreads();

    // Last-block finalize
    __shared__ bool is_last;
    if (tid == 0) {
        __threadfence();
        unsigned int old = atomicAdd(&g_ticket, 1u);
        is_last = (old == (unsigned int)(GRID_BLOCKS - 1));
    }
    __syncthreads();

    if (is_last && tid == 0) {
        __threadfence();
        float total = 0.0f;
        #pragma unroll
        for (int bb = 0; bb < NB; bb++) {
            float s = 0.0f;
            #pragma unroll
            for (int k = 0; k < NK; k++)
                s += g_acc[bb][k] / (g_acc[bb][4 + k] + 1e-8f);
            total += (float)NK - s;
        }
        out[0] = total * (1.0f / NB);
        #pragma unroll
        for (int j = 0; j < NB * 8; j++) ((float*)g_acc)[j] = 0.0f;
        __threadfence();
        g_ticket = 0u;
    }
}

extern "C" void kernel_launch(void* const* d_in, const int* in_sizes, int n_in,
                              void* d_out, int out_size) {
    const float* image = (const float*)d_in[0];
    const float* enc   = (const float*)d_in[1];
    float* out = (float*)d_out;

    dim3 blk(32, 4, 1);
    dim3 grd(IMG_W / TILE_W, IMG_H / TILE_H, NB);
    sncl_fused_kernel<<<grd, blk>>>(image, enc, out);
}